// round 7
// baseline (speedup 1.0000x reference)
#include <cuda_runtime.h>
#include <cuda_bf16.h>
#include <cstdint>

// HopfieldTSP: x_1000 = sign(w @ x0). Iterations 2..1000 are a provable fixed
// point (diagonal 2*rowsum_i ~ 8192 dominates |sum_j adj_ij*(+-1)| <= rowsum_i),
// so one fused pass computes rowsum_i and dot_i = (adj@x0)_i, then
//   s_i = (2*rowsum_i + adj_ii)*x0_i - dot_i ;  out_i = sign(s_i).
//
// R7: the per-thread LDG path plateaus at ~5.7TB/s across every SM-side shape
// tried (R2/R5/R6). Switch hardware paths: cp.async.bulk (TMA/UBLKCP) streams
// each block's 16 rows as 64 x 8KB chunks through a 4-stage smem ring with
// per-stage mbarriers. Copy-engine provides the MLP; consumers just drain.

#define N_CITIES 8192
#define THREADS 256
#define ROWS_PER_BLOCK 16
#define NBLK (N_CITIES / ROWS_PER_BLOCK)      // 512
#define CHUNK_BYTES 8192
#define CHUNK_F4 (CHUNK_BYTES / 16)           // 512 float4
#define CHUNKS_PER_ROW (N_CITIES * 4 / CHUNK_BYTES)  // 4
#define TOTAL_CHUNKS (ROWS_PER_BLOCK * CHUNKS_PER_ROW) // 64
#define STAGES 4

__device__ __forceinline__ uint32_t smem_u32(const void* p) {
    uint32_t a;
    asm("{ .reg .u64 t; cvta.to.shared.u64 t, %1; cvt.u32.u64 %0, t; }"
        : "=r"(a) : "l"(p));
    return a;
}

__device__ __forceinline__ void mbar_init(uint32_t mbar, uint32_t cnt) {
    asm volatile("mbarrier.init.shared.b64 [%0], %1;" :: "r"(mbar), "r"(cnt) : "memory");
}

__device__ __forceinline__ void mbar_expect_tx(uint32_t mbar, uint32_t bytes) {
    asm volatile("mbarrier.arrive.expect_tx.shared.b64 _, [%0], %1;"
                 :: "r"(mbar), "r"(bytes) : "memory");
}

__device__ __forceinline__ void bulk_ld(uint32_t dst, const void* src,
                                        uint32_t bytes, uint32_t mbar) {
    asm volatile("cp.async.bulk.shared::cluster.global.mbarrier::complete_tx::bytes "
                 "[%0], [%1], %2, [%3];"
                 :: "r"(dst), "l"(src), "r"(bytes), "r"(mbar) : "memory");
}

__device__ __forceinline__ void mbar_wait(uint32_t mbar, uint32_t parity) {
    asm volatile(
        "{\n\t"
        ".reg .pred P;\n\t"
        "WL_%=:\n\t"
        "mbarrier.try_wait.parity.acquire.cta.shared::cta.b64 P, [%0], %1, 0x989680;\n\t"
        "@P bra.uni WD_%=;\n\t"
        "bra.uni WL_%=;\n\t"
        "WD_%=:\n\t"
        "}" :: "r"(mbar), "r"(parity) : "memory");
}

__global__ void __launch_bounds__(THREADS, 4)
hopfield_tma_kernel(const float* __restrict__ adj,
                    const float* __restrict__ x,
                    float* __restrict__ out) {
    __shared__ alignas(128) float4 buf[STAGES][CHUNK_F4];  // 32 KB ring
    __shared__ alignas(8) uint64_t mbar_s[STAGES];
    __shared__ float red_rs[THREADS / 32], red_dot[THREADS / 32];

    const int tid  = threadIdx.x;
    const int warp = tid >> 5;
    const int lane = tid & 31;

    uint32_t mb[STAGES], bp[STAGES];
    #pragma unroll
    for (int s = 0; s < STAGES; s++) {
        mb[s] = smem_u32(&mbar_s[s]);
        bp[s] = smem_u32(&buf[s][0]);
    }

    if (tid == 0) {
        #pragma unroll
        for (int s = 0; s < STAGES; s++) mbar_init(mb[s], 1);
    }
    asm volatile("fence.proxy.async.shared::cta;" ::: "memory");
    __syncthreads();

    const int row0 = blockIdx.x * ROWS_PER_BLOCK;
    const char* src0 = reinterpret_cast<const char*>(adj)
                       + (size_t)row0 * N_CITIES * sizeof(float);

    // Prologue: fill all 4 stages.
    if (tid == 0) {
        #pragma unroll
        for (int c = 0; c < STAGES; c++) {
            mbar_expect_tx(mb[c], CHUNK_BYTES);
            bulk_ld(bp[c], src0 + (size_t)c * CHUNK_BYTES, CHUNK_BYTES, mb[c]);
        }
    }

    const float4* x4 = reinterpret_cast<const float4*>(x);
    float rs = 0.0f, dot = 0.0f;

    for (int c = 0; c < TOTAL_CHUNKS; c++) {
        const int stage  = c & (STAGES - 1);
        const int parity = (c >> 2) & 1;
        mbar_wait(mb[stage], parity);

        const int k  = c & (CHUNKS_PER_ROW - 1);   // chunk within row
        const int xb = k * CHUNK_F4;
        float4 a0  = buf[stage][tid];
        float4 a1  = buf[stage][tid + THREADS];
        float4 xv0 = __ldg(&x4[xb + tid]);
        float4 xv1 = __ldg(&x4[xb + tid + THREADS]);
        rs  += (a0.x + a0.y) + (a0.z + a0.w) + (a1.x + a1.y) + (a1.z + a1.w);
        dot += a0.x * xv0.x + a0.y * xv0.y + a0.z * xv0.z + a0.w * xv0.w
             + a1.x * xv1.x + a1.y * xv1.y + a1.z * xv1.z + a1.w * xv1.w;

        __syncthreads();  // whole block done reading this stage
        if (tid == 0 && c + STAGES < TOTAL_CHUNKS) {
            mbar_expect_tx(mb[stage], CHUNK_BYTES);
            bulk_ld(bp[stage], src0 + (size_t)(c + STAGES) * CHUNK_BYTES,
                    CHUNK_BYTES, mb[stage]);
        }

        if (k == CHUNKS_PER_ROW - 1) {
            // End of row: block reduction of (rs, dot).
            #pragma unroll
            for (int o = 16; o > 0; o >>= 1) {
                rs  += __shfl_xor_sync(0xFFFFFFFFu, rs, o);
                dot += __shfl_xor_sync(0xFFFFFFFFu, dot, o);
            }
            if (lane == 0) { red_rs[warp] = rs; red_dot[warp] = dot; }
            __syncthreads();
            if (warp == 0 && lane < THREADS / 32) {
                float r = red_rs[lane], d = red_dot[lane];
                #pragma unroll
                for (int o = 4; o > 0; o >>= 1) {
                    r += __shfl_xor_sync(0xFFu, r, o);
                    d += __shfl_xor_sync(0xFFu, d, o);
                }
                if (lane == 0) {
                    const int row = row0 + (c >> 2);
                    float aii = __ldg(adj + (size_t)row * N_CITIES + row);
                    float xi  = __ldg(x + row);
                    float s   = (2.0f * r + aii) * xi - d;
                    out[row] = (s > 0.0f) ? 1.0f : ((s < 0.0f) ? -1.0f : 0.0f);
                }
            }
            rs = 0.0f;
            dot = 0.0f;
        }
    }
}

extern "C" void kernel_launch(void* const* d_in, const int* in_sizes, int n_in,
                              void* d_out, int out_size) {
    const float* adj = (const float*)d_in[0];   // [8192, 8192] fp32 row-major
    const float* x   = (const float*)d_in[1];   // [8192] fp32
    float* out       = (float*)d_out;           // [8192] fp32

    hopfield_tma_kernel<<<NBLK, THREADS>>>(adj, x, out);
}

// round 8
// speedup vs baseline: 1.7474x; 1.7474x over previous
#include <cuda_runtime.h>
#include <cuda_bf16.h>

// HopfieldTSP: x_1000 = sign(w @ x0). Iterations 2..1000 are a provable fixed
// point (diagonal 2*rowsum_i ~ 8192 dominates |sum_j adj_ij*(+-1)| <= rowsum_i),
// so one fused pass computes rowsum_i and dot_i = (adj@x0)_i, then
//   s_i = (2*rowsum_i + adj_ii)*x0_i - dot_i ;  out_i = sign(s_i).
//
// R8: single-variable change from the best kernel (R5): adj stream via
// __ldcv — the cache-op the B300 microarch doc names as the path that hits
// the measured ~6300 B/cyc chip cap ("LDG.cv ≡ TMA"). Read-once stream gets
// zero L1/L2 allocation bookkeeping. Everything else identical to R5.

#define N_CITIES 8192
#define THREADS 256
#define ROWS_PER_BLOCK (THREADS / 32)   // 8
#define ROW4 (N_CITIES / 4)             // 2048 float4 per row

__global__ void __launch_bounds__(THREADS, 8)
hopfield_fused_kernel(const float* __restrict__ adj,
                      const float* __restrict__ x,
                      float* __restrict__ out) {
    const int warp = threadIdx.x >> 5;
    const int lane = threadIdx.x & 31;
    const int row  = blockIdx.x * ROWS_PER_BLOCK + warp;

    const float4* arow = reinterpret_cast<const float4*>(adj + (size_t)row * N_CITIES);
    const float4* x4   = reinterpret_cast<const float4*>(x);

    // 64 trips per lane. adj: __ldcv (no cache allocation — pure stream,
    // the documented cap-hitting path); x: __ldg, hot in L1.
    float rs = 0.0f, dot = 0.0f;
    #pragma unroll 2
    for (int j = lane; j < ROW4; j += 32) {
        float4 a  = __ldcv(&arow[j]);
        float4 xv = __ldg(&x4[j]);
        rs  += (a.x + a.y) + (a.z + a.w);
        dot += a.x * xv.x + a.y * xv.y + a.z * xv.z + a.w * xv.w;
    }

    #pragma unroll
    for (int o = 16; o > 0; o >>= 1) {
        rs  += __shfl_xor_sync(0xFFFFFFFFu, rs, o);
        dot += __shfl_xor_sync(0xFFFFFFFFu, dot, o);
    }

    if (lane == 0) {
        float aii = __ldg(adj + (size_t)row * N_CITIES + row);
        float xi  = __ldg(x + row);
        float s   = (2.0f * rs + aii) * xi - dot;
        out[row] = (s > 0.0f) ? 1.0f : ((s < 0.0f) ? -1.0f : 0.0f);
    }
}

extern "C" void kernel_launch(void* const* d_in, const int* in_sizes, int n_in,
                              void* d_out, int out_size) {
    const float* adj = (const float*)d_in[0];   // [8192, 8192] fp32 row-major
    const float* x   = (const float*)d_in[1];   // [8192] fp32
    float* out       = (float*)d_out;           // [8192] fp32

    hopfield_fused_kernel<<<N_CITIES / ROWS_PER_BLOCK, THREADS>>>(adj, x, out);
}